// round 1
// baseline (speedup 1.0000x reference)
#include <cuda_runtime.h>
#include <math.h>

// ---------------- precomputed composed-weight scratch ----------------
// Layout (floats), 16B-aligned groups where float4-loaded:
//  W3  [4][4][4][12] : 0    .. 768   (w padded 9->12)
//  G2  [4][12]       : 768  .. 816
//  Q   [4][4]        : 816  .. 832
//  q0                : 832
//  A1  [4][5]        : 836  .. 856
//  B1  [4][5]        : 856  .. 876
//  c5  [5]           : 876  .. 881
//  H   [5][12]       : 884  .. 944   (w padded 9->12)
//  Cm  [5][4]        : 944  .. 964
//  r5  [5]           : 964  .. 969
#define W3_OFF 0
#define G2_OFF 768
#define Q_OFF  816
#define Q0_OFF 832
#define A1_OFF 836
#define B1_OFF 856
#define C5_OFF 876
#define H_OFF  884
#define CM_OFF 944
#define R5_OFF 964
#define PREP_SIZE 976

__device__ float g_prep[PREP_SIZE];

__global__ void prep_kernel(const float* __restrict__ w1_000, const float* __restrict__ w1_110,
                            const float* __restrict__ w1_011, const float* __restrict__ w1_101,
                            const float* __restrict__ w1_111, const float* __restrict__ w2_000,
                            const float* __restrict__ w2_110, const float* __restrict__ w2_011,
                            const float* __restrict__ w2_101, const float* __restrict__ w2_111)
{
    const float C1_000 = (float)sqrt(1.0/17.0);
    const float C1_110 = (float)(sqrt(1.0/17.0)/sqrt(3.0));
    const float C1_011 = (float)(sqrt(3.0/9.0)/sqrt(3.0));
    const float C1_101 = C1_011;
    const float C1_111 = (float)(sqrt(3.0/9.0)/sqrt(6.0));
    const float C2_000 = (float)sqrt(1.0/85.0);
    const float C2_110 = (float)(sqrt(1.0/85.0)/sqrt(3.0));
    const float C2_011 = (float)(sqrt(3.0/45.0)/sqrt(3.0));
    const float C2_101 = C2_011;
    const float C2_111 = (float)(sqrt(3.0/45.0)/sqrt(6.0));

    int tid = threadIdx.x;

    // W3[u][v][t][w] = C2000*C1000 * sum_m w1_000[u,v,m] * w2_000[m,t,w]
    if (tid < 576) {
        int w = tid % 9, t = (tid/9) % 4, v = (tid/36) % 4, u = tid/144;
        float s = 0.f;
        #pragma unroll 4
        for (int m = 0; m < 20; m++)
            s += w1_000[(u*4+v)*20 + m] * w2_000[(m*4+t)*9 + w];
        g_prep[W3_OFF + ((u*4+v)*4 + t)*12 + w] = C2_000 * C1_000 * s;
    }
    // G2[t][w] = C2000*C1110 * sum_m w1_110[m] * w2_000[m,t,w]
    if (tid < 36) {
        int w = tid % 9, t = tid/9;
        float s = 0.f;
        for (int m = 0; m < 20; m++) s += w1_110[m] * w2_000[(m*4+t)*9 + w];
        g_prep[G2_OFF + t*12 + w] = C2_000 * C1_110 * s;
    }
    // Q[u][v] = C2011*C1000 * sum_m w1_000[u,v,m] * w2_011[m]
    if (tid < 16) {
        float s = 0.f;
        for (int m = 0; m < 20; m++) s += w1_000[tid*20 + m] * w2_011[m];
        g_prep[Q_OFF + tid] = C2_011 * C1_000 * s;
    }
    if (tid == 0) {
        float s = 0.f;
        for (int m = 0; m < 20; m++) s += w1_110[m] * w2_011[m];
        g_prep[Q0_OFF] = C2_011 * C1_110 * s;
    }
    if (tid < 20) g_prep[A1_OFF + tid] = C1_011 * w1_011[tid];   // [u][w5]
    if (tid < 20) g_prep[B1_OFF + tid] = C1_101 * w1_101[tid];   // [v][w5]
    if (tid < 5)  g_prep[C5_OFF + tid] = C1_111 * w1_111[tid];
    if (tid < 45) { int u = tid/9, w = tid%9; g_prep[H_OFF + u*12 + w] = C2_110 * w2_110[tid]; }
    if (tid < 20) g_prep[CM_OFF + tid] = C2_101 * w2_101[tid];   // [u5][v4]
    if (tid < 5)  g_prep[R5_OFF + tid] = C2_111 * w2_111[tid];
}

// ---------------- main kernel ----------------
__global__ __launch_bounds__(256)
void dock_kernel(const float* __restrict__ lig, const float* __restrict__ rec,
                 float* __restrict__ out, int B)
{
    __shared__ __align__(16) float sw[PREP_SIZE];
    for (int j = threadIdx.x; j < PREP_SIZE; j += 256) sw[j] = g_prep[j];
    __syncthreads();

    int i = blockIdx.x * 256 + threadIdx.x;
    if (i >= B) return;

    const float4* L = reinterpret_cast<const float4*>(lig) + (size_t)i*3;
    const float4* R = reinterpret_cast<const float4*>(rec) + (size_t)i*3;
    float4 l0 = L[0], l1 = L[1], l2 = L[2];
    float4 r0 = R[0], r1 = R[1], r2 = R[2];

    // atoms 1..3 only (atom 0 unused by the model)
    float e1x = l0.w - r0.w, e1y = l1.x - r1.x, e1z = l1.y - r1.y;
    float e2x = l1.z - r1.z, e2y = l1.w - r1.w, e2z = l2.x - r2.x;
    float e3x = l2.y - r2.y, e3y = l2.z - r2.z, e3z = l2.w - r2.w;

    const float COEFF = -0.18f;                    // -0.5/(5/3)^2
    const float OF1 = 5.f/3.f, OF2 = 10.f/3.f, OF3 = 5.f;

    float s1[4], s2[4], s3[4];
    float v1x,v1y,v1z, v2x,v2y,v2z, v3x,v3y,v3z;
    {
        float d2 = e1x*e1x + e1y*e1y + e1z*e1z;
        float rs = rsqrtf(d2); float d = d2*rs;
        v1x = e1x*rs; v1y = e1y*rs; v1z = e1z*rs;
        float t0 = d,     t1 = d-OF1, t2 = d-OF2, t3 = d-OF3;
        s1[0]=__expf(COEFF*t0*t0); s1[1]=__expf(COEFF*t1*t1);
        s1[2]=__expf(COEFF*t2*t2); s1[3]=__expf(COEFF*t3*t3);
    }
    {
        float d2 = e2x*e2x + e2y*e2y + e2z*e2z;
        float rs = rsqrtf(d2); float d = d2*rs;
        v2x = e2x*rs; v2y = e2y*rs; v2z = e2z*rs;
        float t0 = d,     t1 = d-OF1, t2 = d-OF2, t3 = d-OF3;
        s2[0]=__expf(COEFF*t0*t0); s2[1]=__expf(COEFF*t1*t1);
        s2[2]=__expf(COEFF*t2*t2); s2[3]=__expf(COEFF*t3*t3);
    }
    {
        float d2 = e3x*e3x + e3y*e3y + e3z*e3z;
        float rs = rsqrtf(d2); float d = d2*rs;
        v3x = e3x*rs; v3y = e3y*rs; v3z = e3z*rs;
        float t0 = d,     t1 = d-OF1, t2 = d-OF2, t3 = d-OF3;
        s3[0]=__expf(COEFF*t0*t0); s3[1]=__expf(COEFF*t1*t1);
        s3[2]=__expf(COEFF*t2*t2); s3[3]=__expf(COEFF*t3*t3);
    }

    float dot12 = v1x*v2x + v1y*v2y + v1z*v2z;
    float crx = v1y*v2z - v1z*v2y;
    float cry = v1z*v2x - v1x*v2z;
    float crz = v1x*v2y - v1y*v2x;

    float acc[9];
    #pragma unroll
    for (int w = 0; w < 9; w++) acc[w] = 0.f;

    // Fused trilinear contraction: replaces both big einsums (S never materialized)
    #pragma unroll
    for (int u = 0; u < 4; u++) {
        #pragma unroll
        for (int v = 0; v < 4; v++) {
            float pv = s1[u] * s2[v];
            #pragma unroll
            for (int t = 0; t < 4; t++) {
                float f = pv * s3[t];
                const float4* wr = reinterpret_cast<const float4*>(&sw[W3_OFF + ((u*4+v)*4 + t)*12]);
                float4 wa = wr[0], wb = wr[1], wc = wr[2];
                acc[0] += wa.x*f; acc[1] += wa.y*f; acc[2] += wa.z*f; acc[3] += wa.w*f;
                acc[4] += wb.x*f; acc[5] += wb.y*f; acc[6] += wb.z*f; acc[7] += wb.w*f;
                acc[8] += wc.x*f;
            }
        }
    }

    // dot12 * (G2 . s3) term
    #pragma unroll
    for (int t = 0; t < 4; t++) {
        float f = dot12 * s3[t];
        const float4* gr = reinterpret_cast<const float4*>(&sw[G2_OFF + t*12]);
        float4 ga = gr[0], gb = gr[1], gc = gr[2];
        acc[0] += ga.x*f; acc[1] += ga.y*f; acc[2] += ga.z*f; acc[3] += ga.w*f;
        acc[4] += gb.x*f; acc[5] += gb.y*f; acc[6] += gb.z*f; acc[7] += gb.w*f;
        acc[8] += gc.x*f;
    }

    // V[w][k] = (A1.s1)_w * v2 + (B1.s2)_w * v1 + c5_w * cr12   (constants folded)
    float V[5][3];
    #pragma unroll
    for (int w = 0; w < 5; w++) {
        float aw = sw[A1_OFF+0*5+w]*s1[0] + sw[A1_OFF+1*5+w]*s1[1]
                 + sw[A1_OFF+2*5+w]*s1[2] + sw[A1_OFF+3*5+w]*s1[3];
        float bw = sw[B1_OFF+0*5+w]*s2[0] + sw[B1_OFF+1*5+w]*s2[1]
                 + sw[B1_OFF+2*5+w]*s2[2] + sw[B1_OFF+3*5+w]*s2[3];
        float cw = sw[C5_OFF+w];
        V[w][0] = aw*v2x + bw*v1x + cw*crx;
        V[w][1] = aw*v2y + bw*v1y + cw*cry;
        V[w][2] = aw*v2z + bw*v1z + cw*crz;
    }

    // S2 += H^T . (V . v3)
    #pragma unroll
    for (int u = 0; u < 5; u++) {
        float vd = V[u][0]*v3x + V[u][1]*v3y + V[u][2]*v3z;
        const float4* hr = reinterpret_cast<const float4*>(&sw[H_OFF + u*12]);
        float4 ha = hr[0], hb = hr[1], hc = hr[2];
        acc[0] += ha.x*vd; acc[1] += ha.y*vd; acc[2] += ha.z*vd; acc[3] += ha.w*vd;
        acc[4] += hb.x*vd; acc[5] += hb.y*vd; acc[6] += hb.z*vd; acc[7] += hb.w*vd;
        acc[8] += hc.x*vd;
    }

    // scalarS = C2011 * (w2_011 . S), composed:  Q:(s1 x s2) + q0*dot12
    float scalarS = sw[Q0_OFF] * dot12;
    #pragma unroll
    for (int u = 0; u < 4; u++)
        #pragma unroll
        for (int v = 0; v < 4; v++)
            scalarS += sw[Q_OFF + u*4 + v] * (s1[u] * s2[v]);

    // V2 = scalarS*v3 + sum_u (Cm[u].s3) * V[u] + cross(sum_u r5_u V[u], v3)
    float t2x = scalarS*v3x, t2y = scalarS*v3y, t2z = scalarS*v3z;
    float wx = 0.f, wy = 0.f, wz = 0.f;
    #pragma unroll
    for (int u = 0; u < 5; u++) {
        float cu = sw[CM_OFF+u*4+0]*s3[0] + sw[CM_OFF+u*4+1]*s3[1]
                 + sw[CM_OFF+u*4+2]*s3[2] + sw[CM_OFF+u*4+3]*s3[3];
        t2x += cu*V[u][0]; t2y += cu*V[u][1]; t2z += cu*V[u][2];
        float r = sw[R5_OFF+u];
        wx += r*V[u][0]; wy += r*V[u][1]; wz += r*V[u][2];
    }
    t2x += wy*v3z - wz*v3y;
    t2y += wz*v3x - wx*v3z;
    t2z += wx*v3y - wy*v3x;

    // outputs: 4 concatenated [B,3] arrays: s_rot=S2[0:3], s_tr=S2[3:6], t_rot=S2[6:9], t_tr=V2
    float* o0 = out + (size_t)3*i;
    float* o1 = out + (size_t)3*B + (size_t)3*i;
    float* o2 = out + (size_t)6*B + (size_t)3*i;
    float* o3 = out + (size_t)9*B + (size_t)3*i;
    o0[0] = acc[0]; o0[1] = acc[1]; o0[2] = acc[2];
    o1[0] = acc[3]; o1[1] = acc[4]; o1[2] = acc[5];
    o2[0] = acc[6]; o2[1] = acc[7]; o2[2] = acc[8];
    o3[0] = t2x;    o3[1] = t2y;    o3[2] = t2z;
}

extern "C" void kernel_launch(void* const* d_in, const int* in_sizes, int n_in,
                              void* d_out, int out_size)
{
    const float* lig    = (const float*)d_in[0];
    const float* rec    = (const float*)d_in[1];
    const float* w1_000 = (const float*)d_in[2];
    const float* w1_110 = (const float*)d_in[3];
    const float* w1_011 = (const float*)d_in[4];
    const float* w1_101 = (const float*)d_in[5];
    const float* w1_111 = (const float*)d_in[6];
    const float* w2_000 = (const float*)d_in[7];
    const float* w2_110 = (const float*)d_in[8];
    const float* w2_011 = (const float*)d_in[9];
    const float* w2_101 = (const float*)d_in[10];
    const float* w2_111 = (const float*)d_in[11];

    int B = in_sizes[0] / 12;

    prep_kernel<<<1, 576>>>(w1_000, w1_110, w1_011, w1_101, w1_111,
                            w2_000, w2_110, w2_011, w2_101, w2_111);
    dock_kernel<<<(B + 255) / 256, 256>>>(lig, rec, (float*)d_out, B);
}

// round 5
// speedup vs baseline: 1.2871x; 1.2871x over previous
#include <cuda_runtime.h>
#include <math.h>

// ---------------- precomputed composed-weight scratch ----------------
//  W3  [4][4][4][12] : 0    .. 768   (w padded 9->12, pads ZEROED)
//  G2  [4][12]       : 768  .. 816
//  Q   [4][4]        : 816  .. 832
//  q0                : 832
//  A1  [4][5]        : 836  .. 856
//  B1  [4][5]        : 856  .. 876
//  c5  [5]           : 876  .. 881
//  H   [5][12]       : 884  .. 944   (w padded 9->12, pads ZEROED)
//  Cm  [5][4]        : 944  .. 964
//  r5  [5]           : 964  .. 969
#define W3_OFF 0
#define G2_OFF 768
#define Q_OFF  816
#define Q0_OFF 832
#define A1_OFF 836
#define B1_OFF 856
#define C5_OFF 876
#define H_OFF  884
#define CM_OFF 944
#define R5_OFF 964
#define PREP_SIZE 976

__device__ float g_prep[PREP_SIZE];

__global__ void prep_kernel(const float* __restrict__ w1_000, const float* __restrict__ w1_110,
                            const float* __restrict__ w1_011, const float* __restrict__ w1_101,
                            const float* __restrict__ w1_111, const float* __restrict__ w2_000,
                            const float* __restrict__ w2_110, const float* __restrict__ w2_011,
                            const float* __restrict__ w2_101, const float* __restrict__ w2_111)
{
    const float C1_000 = (float)sqrt(1.0/17.0);
    const float C1_110 = (float)(sqrt(1.0/17.0)/sqrt(3.0));
    const float C1_011 = (float)(sqrt(3.0/9.0)/sqrt(3.0));
    const float C1_101 = C1_011;
    const float C1_111 = (float)(sqrt(3.0/9.0)/sqrt(6.0));
    const float C2_000 = (float)sqrt(1.0/85.0);
    const float C2_110 = (float)(sqrt(1.0/85.0)/sqrt(3.0));
    const float C2_011 = (float)(sqrt(3.0/45.0)/sqrt(3.0));
    const float C2_101 = C2_011;
    const float C2_111 = (float)(sqrt(3.0/45.0)/sqrt(6.0));

    int tid = threadIdx.x;

    // zero everything first (padding lanes must be exactly 0 for f32x2 path)
    for (int j = tid; j < PREP_SIZE; j += 576) g_prep[j] = 0.f;
    __syncthreads();

    if (tid < 576) {
        int w = tid % 9, t = (tid/9) % 4, v = (tid/36) % 4, u = tid/144;
        float s = 0.f;
        #pragma unroll 4
        for (int m = 0; m < 20; m++)
            s += w1_000[(u*4+v)*20 + m] * w2_000[(m*4+t)*9 + w];
        g_prep[W3_OFF + ((u*4+v)*4 + t)*12 + w] = C2_000 * C1_000 * s;
    }
    if (tid < 36) {
        int w = tid % 9, t = tid/9;
        float s = 0.f;
        for (int m = 0; m < 20; m++) s += w1_110[m] * w2_000[(m*4+t)*9 + w];
        g_prep[G2_OFF + t*12 + w] = C2_000 * C1_110 * s;
    }
    if (tid < 16) {
        float s = 0.f;
        for (int m = 0; m < 20; m++) s += w1_000[tid*20 + m] * w2_011[m];
        g_prep[Q_OFF + tid] = C2_011 * C1_000 * s;
    }
    if (tid == 0) {
        float s = 0.f;
        for (int m = 0; m < 20; m++) s += w1_110[m] * w2_011[m];
        g_prep[Q0_OFF] = C2_011 * C1_110 * s;
    }
    if (tid < 20) g_prep[A1_OFF + tid] = C1_011 * w1_011[tid];
    if (tid < 20) g_prep[B1_OFF + tid] = C1_101 * w1_101[tid];
    if (tid < 5)  g_prep[C5_OFF + tid] = C1_111 * w1_111[tid];
    if (tid < 45) { int u = tid/9, w = tid%9; g_prep[H_OFF + u*12 + w] = C2_110 * w2_110[tid]; }
    if (tid < 20) g_prep[CM_OFF + tid] = C2_101 * w2_101[tid];
    if (tid < 5)  g_prep[R5_OFF + tid] = C2_111 * w2_111[tid];
}

// ---------------- f32x2 helpers ----------------
typedef unsigned long long u64;

__device__ __forceinline__ u64 pack2(float x, float y) {
    u64 r; asm("mov.b64 %0, {%1, %2};" : "=l"(r) : "f"(x), "f"(y)); return r;
}
__device__ __forceinline__ u64 mul2(u64 a, u64 b) {
    u64 r; asm("mul.rn.f32x2 %0, %1, %2;" : "=l"(r) : "l"(a), "l"(b)); return r;
}
__device__ __forceinline__ void fma2(u64 &d, u64 a, u64 b) {
    asm("fma.rn.f32x2 %0, %1, %2, %0;" : "+l"(d) : "l"(a), "l"(b));
}
__device__ __forceinline__ float2 unpk(u64 v) {
    float2 r; asm("mov.b64 {%0, %1}, %2;" : "=f"(r.x), "=f"(r.y) : "l"(v)); return r;
}

// ---------------- main kernel: 2 rows per thread ----------------
__global__ __launch_bounds__(128)
void dock_kernel(const float* __restrict__ lig, const float* __restrict__ rec,
                 float* __restrict__ out, int B)
{
    __shared__ __align__(16) float sw[PREP_SIZE];
    for (int j = threadIdx.x; j < PREP_SIZE; j += 128) sw[j] = g_prep[j];
    __syncthreads();

    int i = blockIdx.x * 128 + threadIdx.x;
    int r0 = 2 * i;
    if (r0 >= B) return;
    bool two = (r0 + 1 < B);

    const float COEFF = -0.18f;                    // -0.5/(5/3)^2
    const float OF1 = 5.f/3.f, OF2 = 10.f/3.f, OF3 = 5.f;

    // sA[r][edge][gauss], vA[r][edge][xyz]
    float sA[2][3][4], vA[2][3][3];
    #pragma unroll
    for (int r = 0; r < 2; r++) {
        int row = (two && r) ? (r0 + 1) : r0;
        const float4* L = reinterpret_cast<const float4*>(lig) + (size_t)row*3;
        const float4* R = reinterpret_cast<const float4*>(rec) + (size_t)row*3;
        float4 l0=L[0], l1=L[1], l2=L[2];
        float4 q0=R[0], q1=R[1], q2=R[2];
        float ev[9];
        ev[0]=l0.w-q0.w; ev[1]=l1.x-q1.x; ev[2]=l1.y-q1.y;
        ev[3]=l1.z-q1.z; ev[4]=l1.w-q1.w; ev[5]=l2.x-q2.x;
        ev[6]=l2.y-q2.y; ev[7]=l2.z-q2.z; ev[8]=l2.w-q2.w;
        #pragma unroll
        for (int e = 0; e < 3; e++) {
            float ex=ev[3*e], ey=ev[3*e+1], ez=ev[3*e+2];
            float d2 = ex*ex + ey*ey + ez*ez;
            float rs = rsqrtf(d2); float d = d2*rs;
            vA[r][e][0]=ex*rs; vA[r][e][1]=ey*rs; vA[r][e][2]=ez*rs;
            float t1=d-OF1, t2=d-OF2, t3=d-OF3;
            sA[r][e][0]=__expf(COEFF*d*d);
            sA[r][e][1]=__expf(COEFF*t1*t1);
            sA[r][e][2]=__expf(COEFF*t2*t2);
            sA[r][e][3]=__expf(COEFF*t3*t3);
        }
    }

    float dot12[2], cr[2][3];
    u64 s3p[2][4], d12p[2];
    #pragma unroll
    for (int r = 0; r < 2; r++) {
        dot12[r] = vA[r][0][0]*vA[r][1][0] + vA[r][0][1]*vA[r][1][1] + vA[r][0][2]*vA[r][1][2];
        cr[r][0] = vA[r][0][1]*vA[r][1][2] - vA[r][0][2]*vA[r][1][1];
        cr[r][1] = vA[r][0][2]*vA[r][1][0] - vA[r][0][0]*vA[r][1][2];
        cr[r][2] = vA[r][0][0]*vA[r][1][1] - vA[r][0][1]*vA[r][1][0];
        #pragma unroll
        for (int t = 0; t < 4; t++) s3p[r][t] = pack2(sA[r][2][t], sA[r][2][t]);
        d12p[r] = pack2(dot12[r], dot12[r]);
    }

    // packed accumulators: 5 pairs/row cover acc[0..9] (acc[9] is zero-weight junk)
    u64 accp[2][5];
    #pragma unroll
    for (int r = 0; r < 2; r++)
        #pragma unroll
        for (int k = 0; k < 5; k++) accp[r][k] = 0ull;

    // Fused trilinear contraction (both big einsums; S never materialized)
    #pragma unroll
    for (int u = 0; u < 4; u++) {
        #pragma unroll
        for (int v = 0; v < 4; v++) {
            u64 pvp[2];
            #pragma unroll
            for (int r = 0; r < 2; r++) {
                float pv = sA[r][0][u] * sA[r][1][v];
                pvp[r] = pack2(pv, pv);
            }
            #pragma unroll
            for (int t = 0; t < 4; t++) {
                const float* wb = &sw[W3_OFF + ((u*4+v)*4 + t)*12];
                ulonglong2 p0 = *reinterpret_cast<const ulonglong2*>(wb);
                ulonglong2 p1 = *reinterpret_cast<const ulonglong2*>(wb + 4);
                u64 p2 = *reinterpret_cast<const u64*>(wb + 8);
                #pragma unroll
                for (int r = 0; r < 2; r++) {
                    u64 f2 = mul2(pvp[r], s3p[r][t]);
                    fma2(accp[r][0], p0.x, f2);
                    fma2(accp[r][1], p0.y, f2);
                    fma2(accp[r][2], p1.x, f2);
                    fma2(accp[r][3], p1.y, f2);
                    fma2(accp[r][4], p2,   f2);
                }
            }
        }
    }

    // dot12 * (G2 . s3)
    #pragma unroll
    for (int t = 0; t < 4; t++) {
        const float* gb = &sw[G2_OFF + t*12];
        ulonglong2 p0 = *reinterpret_cast<const ulonglong2*>(gb);
        ulonglong2 p1 = *reinterpret_cast<const ulonglong2*>(gb + 4);
        u64 p2 = *reinterpret_cast<const u64*>(gb + 8);
        #pragma unroll
        for (int r = 0; r < 2; r++) {
            u64 f2 = mul2(d12p[r], s3p[r][t]);
            fma2(accp[r][0], p0.x, f2);
            fma2(accp[r][1], p0.y, f2);
            fma2(accp[r][2], p1.x, f2);
            fma2(accp[r][3], p1.y, f2);
            fma2(accp[r][4], p2,   f2);
        }
    }

    // V[r][w][k] = (A1.s1)_w * v2 + (B1.s2)_w * v1 + c5_w * cr12
    float V[2][5][3];
    #pragma unroll
    for (int w = 0; w < 5; w++) {
        float a0=sw[A1_OFF+0*5+w], a1=sw[A1_OFF+1*5+w], a2=sw[A1_OFF+2*5+w], a3=sw[A1_OFF+3*5+w];
        float b0=sw[B1_OFF+0*5+w], b1=sw[B1_OFF+1*5+w], b2=sw[B1_OFF+2*5+w], b3=sw[B1_OFF+3*5+w];
        float cw = sw[C5_OFF + w];
        #pragma unroll
        for (int r = 0; r < 2; r++) {
            float aw = a0*sA[r][0][0] + a1*sA[r][0][1] + a2*sA[r][0][2] + a3*sA[r][0][3];
            float bw = b0*sA[r][1][0] + b1*sA[r][1][1] + b2*sA[r][1][2] + b3*sA[r][1][3];
            V[r][w][0] = aw*vA[r][1][0] + bw*vA[r][0][0] + cw*cr[r][0];
            V[r][w][1] = aw*vA[r][1][1] + bw*vA[r][0][1] + cw*cr[r][1];
            V[r][w][2] = aw*vA[r][1][2] + bw*vA[r][0][2] + cw*cr[r][2];
        }
    }

    // S2 += H^T . (V . v3)   (packed)
    #pragma unroll
    for (int u = 0; u < 5; u++) {
        const float* hb = &sw[H_OFF + u*12];
        ulonglong2 p0 = *reinterpret_cast<const ulonglong2*>(hb);
        ulonglong2 p1 = *reinterpret_cast<const ulonglong2*>(hb + 4);
        u64 p2 = *reinterpret_cast<const u64*>(hb + 8);
        #pragma unroll
        for (int r = 0; r < 2; r++) {
            float vd = V[r][u][0]*vA[r][2][0] + V[r][u][1]*vA[r][2][1] + V[r][u][2]*vA[r][2][2];
            u64 vd2 = pack2(vd, vd);
            fma2(accp[r][0], p0.x, vd2);
            fma2(accp[r][1], p0.y, vd2);
            fma2(accp[r][2], p1.x, vd2);
            fma2(accp[r][3], p1.y, vd2);
            fma2(accp[r][4], p2,   vd2);
        }
    }

    // scalarS = Q:(s1 x s2) + q0*dot12
    float scal[2];
    scal[0] = sw[Q0_OFF] * dot12[0];
    scal[1] = sw[Q0_OFF] * dot12[1];
    #pragma unroll
    for (int u = 0; u < 4; u++) {
        #pragma unroll
        for (int v = 0; v < 4; v++) {
            float q = sw[Q_OFF + u*4 + v];
            #pragma unroll
            for (int r = 0; r < 2; r++)
                scal[r] += q * (sA[r][0][u] * sA[r][1][v]);
        }
    }

    // unpack S2 accumulators
    float val[2][12];
    #pragma unroll
    for (int r = 0; r < 2; r++) {
        #pragma unroll
        for (int k = 0; k < 5; k++) {
            float2 f = unpk(accp[r][k]);
            if (2*k   < 9) val[r][2*k]   = f.x;
            if (2*k+1 < 9) val[r][2*k+1] = f.y;
        }
    }

    // V2 = scalarS*v3 + sum_u (Cm[u].s3) V[u] + cross(sum_u r5_u V[u], v3)
    float t2[2][3], wv[2][3];
    #pragma unroll
    for (int r = 0; r < 2; r++) {
        t2[r][0]=scal[r]*vA[r][2][0]; t2[r][1]=scal[r]*vA[r][2][1]; t2[r][2]=scal[r]*vA[r][2][2];
        wv[r][0]=0.f; wv[r][1]=0.f; wv[r][2]=0.f;
    }
    #pragma unroll
    for (int u = 0; u < 5; u++) {
        float c0=sw[CM_OFF+u*4+0], c1=sw[CM_OFF+u*4+1], c2=sw[CM_OFF+u*4+2], c3=sw[CM_OFF+u*4+3];
        float ru = sw[R5_OFF + u];
        #pragma unroll
        for (int r = 0; r < 2; r++) {
            float cu = c0*sA[r][2][0] + c1*sA[r][2][1] + c2*sA[r][2][2] + c3*sA[r][2][3];
            t2[r][0] += cu*V[r][u][0]; t2[r][1] += cu*V[r][u][1]; t2[r][2] += cu*V[r][u][2];
            wv[r][0] += ru*V[r][u][0]; wv[r][1] += ru*V[r][u][1]; wv[r][2] += ru*V[r][u][2];
        }
    }
    #pragma unroll
    for (int r = 0; r < 2; r++) {
        val[r][9]  = t2[r][0] + wv[r][1]*vA[r][2][2] - wv[r][2]*vA[r][2][1];
        val[r][10] = t2[r][1] + wv[r][2]*vA[r][2][0] - wv[r][0]*vA[r][2][2];
        val[r][11] = t2[r][2] + wv[r][0]*vA[r][2][1] - wv[r][1]*vA[r][2][0];
    }

    // stores: 4 concatenated [B,3] regions
    if (two && ((B & 1) == 0)) {
        #pragma unroll
        for (int g = 0; g < 4; g++) {
            float2* o = reinterpret_cast<float2*>(out + (size_t)(3*g)*B + (size_t)3*r0);
            o[0] = make_float2(val[0][3*g+0], val[0][3*g+1]);
            o[1] = make_float2(val[0][3*g+2], val[1][3*g+0]);
            o[2] = make_float2(val[1][3*g+1], val[1][3*g+2]);
        }
    } else {
        #pragma unroll
        for (int g = 0; g < 4; g++) {
            float* o = out + (size_t)(3*g)*B + (size_t)3*r0;
            o[0]=val[0][3*g+0]; o[1]=val[0][3*g+1]; o[2]=val[0][3*g+2];
            if (two) { o[3]=val[1][3*g+0]; o[4]=val[1][3*g+1]; o[5]=val[1][3*g+2]; }
        }
    }
}

extern "C" void kernel_launch(void* const* d_in, const int* in_sizes, int n_in,
                              void* d_out, int out_size)
{
    const float* lig    = (const float*)d_in[0];
    const float* rec    = (const float*)d_in[1];
    const float* w1_000 = (const float*)d_in[2];
    const float* w1_110 = (const float*)d_in[3];
    const float* w1_011 = (const float*)d_in[4];
    const float* w1_101 = (const float*)d_in[5];
    const float* w1_111 = (const float*)d_in[6];
    const float* w2_000 = (const float*)d_in[7];
    const float* w2_110 = (const float*)d_in[8];
    const float* w2_011 = (const float*)d_in[9];
    const float* w2_101 = (const float*)d_in[10];
    const float* w2_111 = (const float*)d_in[11];

    int B = in_sizes[0] / 12;
    int nthreads = (B + 1) / 2;

    prep_kernel<<<1, 576>>>(w1_000, w1_110, w1_011, w1_101, w1_111,
                            w2_000, w2_110, w2_011, w2_101, w2_111);
    dock_kernel<<<(nthreads + 127) / 128, 128>>>(lig, rec, (float*)d_out, B);
}